// round 1
// baseline (speedup 1.0000x reference)
#include <cuda_runtime.h>
#include <math.h>

#define BATCH_N   4096
#define FEAT_D    512
#define NUM_AGES  100
#define TEMP_F    0.1f
#define EPS_F     1e-6f

// ---------------- device scratch (no allocations allowed) ----------------
__device__ float  g_w[BATCH_N * FEAT_D];   // w_j = vb_j - vf_j            (8 MB)
__device__ float  g_sq[BATCH_N];           // ||z_j||^2
__device__ float  g_dw[BATCH_N];           // z_j . w_j
__device__ int    g_ages[BATCH_N];
__device__ double g_acc;

// ---------------- K0: zero accumulator + convert ages (int64/int32 autodetect) ----
__global__ void k_init(const void* __restrict__ ages_raw) {
    __shared__ int s_is64;
    if (threadIdx.x == 0) {
        // If the buffer is int32, reading it as int64 combines two ages:
        // value = lo + hi*2^32; any hi>0 makes it >= NUM_AGES -> detect int32.
        const long long* p = (const long long*)ages_raw;
        int ok = 1;
        for (int t = 0; t < 64; ++t) {
            long long v = p[t];
            if (v < 0 || v >= NUM_AGES) { ok = 0; break; }
        }
        s_is64 = ok;
        g_acc = 0.0;
    }
    __syncthreads();
    const int is64 = s_is64;
    for (int i = threadIdx.x; i < BATCH_N; i += blockDim.x) {
        long long v = is64 ? ((const long long*)ages_raw)[i]
                           : (long long)((const int*)ages_raw)[i];
        g_ages[i] = (int)v;
    }
}

// ---------------- K1: per-sample w_j, dw_j, sq_j  (one block per j, 128 thr) ------
__global__ __launch_bounds__(128) void k_prep(const float* __restrict__ z,
                                              const float* __restrict__ proxies) {
    const int j  = blockIdx.x;
    const int t  = threadIdx.x;
    const int aj = g_ages[j];
    const int an = min(aj + 1, NUM_AGES - 1);
    const int ap = max(aj - 1, 0);
    const float* cc = proxies + (size_t)aj * FEAT_D;
    const float* cn = proxies + (size_t)an * FEAT_D;
    const float* cp = proxies + (size_t)ap * FEAT_D;

    float df[4], db[4];
    float nf2 = 0.f, nb2 = 0.f;
#pragma unroll
    for (int q = 0; q < 4; ++q) {
        int d = t + q * 128;
        float c0 = cc[d];
        df[q] = cn[d] - c0;
        db[q] = cp[d] - c0;
        nf2 += df[q] * df[q];
        nb2 += db[q] * db[q];
    }
    // warp reduce
#pragma unroll
    for (int o = 16; o; o >>= 1) {
        nf2 += __shfl_xor_sync(0xFFFFFFFFu, nf2, o);
        nb2 += __shfl_xor_sync(0xFFFFFFFFu, nb2, o);
    }
    __shared__ float sf[4], sb[4];
    if ((t & 31) == 0) { sf[t >> 5] = nf2; sb[t >> 5] = nb2; }
    __syncthreads();
    nf2 = sf[0] + sf[1] + sf[2] + sf[3];
    nb2 = sb[0] + sb[1] + sb[2] + sb[3];
    const float rf = 1.f / (sqrtf(nf2) + EPS_F);
    const float rb = 1.f / (sqrtf(nb2) + EPS_F);

    float dw = 0.f, sq = 0.f;
#pragma unroll
    for (int q = 0; q < 4; ++q) {
        int d = t + q * 128;
        float wv = db[q] * rb - df[q] * rf;
        g_w[(size_t)j * FEAT_D + d] = wv;
        float zv = z[(size_t)j * FEAT_D + d];
        dw += zv * wv;
        sq += zv * zv;
    }
#pragma unroll
    for (int o = 16; o; o >>= 1) {
        dw += __shfl_xor_sync(0xFFFFFFFFu, dw, o);
        sq += __shfl_xor_sync(0xFFFFFFFFu, sq, o);
    }
    __shared__ float sd[4], ss[4];
    if ((t & 31) == 0) { sd[t >> 5] = dw; ss[t >> 5] = sq; }
    __syncthreads();
    if (t == 0) {
        g_dw[j] = sd[0] + sd[1] + sd[2] + sd[3];
        g_sq[j] = ss[0] + ss[1] + ss[2] + ss[3];
    }
}

// ---------------- K2: fused dual-Gram 64x64 tile + masked softplus epilogue -------
// grid (64, 64): blockIdx.x = j-tile, blockIdx.y = i-tile. 256 threads, each owns a
// 4x4 output sub-tile of BOTH G (= Z Z^T) and Gw (= Z W^T).
__global__ __launch_bounds__(256) void k_main(const float* __restrict__ z) {
    const int i0 = blockIdx.y * 64;
    const int j0 = blockIdx.x * 64;
    const int t  = threadIdx.x;
    const int tx = t & 15;        // 0..15 -> j sub-tile
    const int ty = t >> 4;        // 0..15 -> i sub-tile

    __shared__ __align__(16) float sZi[16][68];
    __shared__ __align__(16) float sZj[16][68];
    __shared__ __align__(16) float sW [16][68];

    float accg[4][4] = {};
    float accw[4][4] = {};

    const int lr = t >> 2;          // 0..63 : row within tile for the loader
    const int lk = (t & 3) * 4;     // 0,4,8,12 : k offset within 16-chunk
    const float* gzi = z   + (size_t)(i0 + lr) * FEAT_D + lk;
    const float* gzj = z   + (size_t)(j0 + lr) * FEAT_D + lk;
    const float* gw  = g_w + (size_t)(j0 + lr) * FEAT_D + lk;

    for (int k0 = 0; k0 < FEAT_D; k0 += 16) {
        float4 vi = *(const float4*)(gzi + k0);
        float4 vj = *(const float4*)(gzj + k0);
        float4 vw = *(const float4*)(gw  + k0);
        __syncthreads();
        sZi[lk + 0][lr] = vi.x; sZi[lk + 1][lr] = vi.y;
        sZi[lk + 2][lr] = vi.z; sZi[lk + 3][lr] = vi.w;
        sZj[lk + 0][lr] = vj.x; sZj[lk + 1][lr] = vj.y;
        sZj[lk + 2][lr] = vj.z; sZj[lk + 3][lr] = vj.w;
        sW [lk + 0][lr] = vw.x; sW [lk + 1][lr] = vw.y;
        sW [lk + 2][lr] = vw.z; sW [lk + 3][lr] = vw.w;
        __syncthreads();
#pragma unroll
        for (int k = 0; k < 16; ++k) {
            float4 a  = *(const float4*)&sZi[k][ty * 4];
            float4 bz = *(const float4*)&sZj[k][tx * 4];
            float4 bw = *(const float4*)&sW [k][tx * 4];
            float av [4] = {a.x,  a.y,  a.z,  a.w };
            float bzv[4] = {bz.x, bz.y, bz.z, bz.w};
            float bwv[4] = {bw.x, bw.y, bw.z, bw.w};
#pragma unroll
            for (int r = 0; r < 4; ++r) {
#pragma unroll
                for (int c = 0; c < 4; ++c) {
                    accg[r][c] += av[r] * bzv[c];
                    accw[r][c] += av[r] * bwv[c];
                }
            }
        }
    }

    // ---- epilogue: masked softplus over this thread's 4x4 pairs ----
    float sqi[4];  int agi[4];
    float sqj[4], dwj[4]; int agj[4];
#pragma unroll
    for (int r = 0; r < 4; ++r) {
        int gi = i0 + ty * 4 + r;
        sqi[r] = g_sq[gi];
        agi[r] = g_ages[gi];
    }
#pragma unroll
    for (int c = 0; c < 4; ++c) {
        int gj = j0 + tx * 4 + c;
        sqj[c] = g_sq[gj];
        dwj[c] = g_dw[gj];
        agj[c] = g_ages[gj];
    }

    float lsum = 0.f;
    const float inv_t = 1.0f / TEMP_F;
#pragma unroll
    for (int r = 0; r < 4; ++r) {
#pragma unroll
        for (int c = 0; c < 4; ++c) {
            if (agi[r] < agj[c]) {
                float d2    = fmaxf(sqi[r] + sqj[c] - 2.f * accg[r][c], 0.f);
                float denom = sqrtf(d2) + EPS_F;
                float arg   = (accw[r][c] - dwj[c]) * inv_t / denom;
                // numerically stable softplus
                lsum += fmaxf(arg, 0.f) + log1pf(__expf(-fabsf(arg)));
            }
        }
    }

    __shared__ float sred[256];
    sred[t] = lsum;
    __syncthreads();
#pragma unroll
    for (int s = 128; s > 0; s >>= 1) {
        if (t < s) sred[t] += sred[t + s];
        __syncthreads();
    }
    if (t == 0) atomicAdd(&g_acc, (double)sred[0]);
}

// ---------------- K3: finalize ----------------
__global__ void k_final(float* __restrict__ out) {
    out[0] = (float)(g_acc / ((double)BATCH_N * (double)(BATCH_N - 1)));
}

extern "C" void kernel_launch(void* const* d_in, const int* in_sizes, int n_in,
                              void* d_out, int out_size) {
    const float* z       = (const float*)d_in[0];
    const void*  ages    = d_in[1];
    const float* proxies = (const float*)d_in[2];
    float* out = (float*)d_out;

    k_init<<<1, 256>>>(ages);
    k_prep<<<BATCH_N, 128>>>(z, proxies);
    dim3 grid(BATCH_N / 64, BATCH_N / 64);
    k_main<<<grid, 256>>>(z);
    k_final<<<1, 1>>>(out);
}

// round 3
// speedup vs baseline: 4.8420x; 4.8420x over previous
#include <cuda_runtime.h>
#include <cuda_bf16.h>
#include <math.h>
#include <stdint.h>

#define BATCH_N   4096
#define FEAT_D    512
#define NUM_AGES  100
#define EPS_F     1e-6f

#define TI 128
#define TJ 128
#define KC 64                       // K chunk (bf16 elems) = 128B rows
#define NCHUNK (FEAT_D / KC)        // 8
#define STAGE_BYTES (3 * 128 * 128) // Zi,Zj,Wj: 3 x 16KB = 49152
#define META 4096
#define SMEM_DYN (META + 2 * STAGE_BYTES + 1024)

#define SW128(o) ((o) ^ (((o) >> 3) & 0x70))

// ---------------- device scratch ----------------
__device__ __nv_bfloat16 g_zb[BATCH_N * FEAT_D];
__device__ __nv_bfloat16 g_wb[BATCH_N * FEAT_D];
__device__ float  g_sq[BATCH_N];
__device__ float  g_dw[BATCH_N];
__device__ int    g_ages[BATCH_N];
__device__ double g_acc;

// ---------------- PTX helpers (all portable at compute_103) ----------------
static __device__ __forceinline__ void ldsm_x4(uint32_t (&r)[4], uint32_t addr) {
    asm volatile("ldmatrix.sync.aligned.m8n8.x4.shared.b16 {%0,%1,%2,%3}, [%4];"
                 : "=r"(r[0]), "=r"(r[1]), "=r"(r[2]), "=r"(r[3]) : "r"(addr));
}
static __device__ __forceinline__ void mma_bf16(float (&c)[4], const uint32_t (&a)[4],
                                                const uint32_t b0, const uint32_t b1) {
    asm volatile(
        "mma.sync.aligned.m16n8k16.row.col.f32.bf16.bf16.f32 "
        "{%0,%1,%2,%3}, {%4,%5,%6,%7}, {%8,%9}, {%0,%1,%2,%3};"
        : "+f"(c[0]), "+f"(c[1]), "+f"(c[2]), "+f"(c[3])
        : "r"(a[0]), "r"(a[1]), "r"(a[2]), "r"(a[3]), "r"(b0), "r"(b1));
}
static __device__ __forceinline__ void cp16(uint32_t dst, const void* src) {
    asm volatile("cp.async.cg.shared.global [%0], [%1], 16;" :: "r"(dst), "l"(src) : "memory");
}

// ---------------- K0: init + age convert (int64/int32 autodetect) ----------------
__global__ void k_init(const void* __restrict__ ages_raw) {
    __shared__ int s_is64;
    if (threadIdx.x == 0) {
        const long long* p = (const long long*)ages_raw;
        int ok = 1;
        for (int t = 0; t < 64; ++t) {
            long long v = p[t];
            if (v < 0 || v >= NUM_AGES) { ok = 0; break; }
        }
        s_is64 = ok;
        g_acc = 0.0;
    }
    __syncthreads();
    const int is64 = s_is64;
    for (int i = threadIdx.x; i < BATCH_N; i += blockDim.x) {
        long long v = is64 ? ((const long long*)ages_raw)[i]
                           : (long long)((const int*)ages_raw)[i];
        g_ages[i] = (int)v;
    }
}

// ---------------- K1: w_j (bf16), z (bf16), dw_j, sq_j ----------------
__global__ __launch_bounds__(128) void k_prep(const float* __restrict__ z,
                                              const float* __restrict__ proxies) {
    const int j  = blockIdx.x;
    const int t  = threadIdx.x;
    const int aj = g_ages[j];
    const int an = min(aj + 1, NUM_AGES - 1);
    const int ap = max(aj - 1, 0);
    const float* cc = proxies + (size_t)aj * FEAT_D;
    const float* cn = proxies + (size_t)an * FEAT_D;
    const float* cp = proxies + (size_t)ap * FEAT_D;

    float df[4], db[4];
    float nf2 = 0.f, nb2 = 0.f;
#pragma unroll
    for (int q = 0; q < 4; ++q) {
        int d = t + q * 128;
        float c0 = cc[d];
        df[q] = cn[d] - c0;
        db[q] = cp[d] - c0;
        nf2 += df[q] * df[q];
        nb2 += db[q] * db[q];
    }
#pragma unroll
    for (int o = 16; o; o >>= 1) {
        nf2 += __shfl_xor_sync(0xFFFFFFFFu, nf2, o);
        nb2 += __shfl_xor_sync(0xFFFFFFFFu, nb2, o);
    }
    __shared__ float sf[4], sb[4];
    if ((t & 31) == 0) { sf[t >> 5] = nf2; sb[t >> 5] = nb2; }
    __syncthreads();
    nf2 = sf[0] + sf[1] + sf[2] + sf[3];
    nb2 = sb[0] + sb[1] + sb[2] + sb[3];
    const float rf = 1.f / (sqrtf(nf2) + EPS_F);
    const float rb = 1.f / (sqrtf(nb2) + EPS_F);

    float dw = 0.f, sq = 0.f;
#pragma unroll
    for (int q = 0; q < 4; ++q) {
        int d = t + q * 128;
        float wv = db[q] * rb - df[q] * rf;
        float zv = z[(size_t)j * FEAT_D + d];
        g_wb[(size_t)j * FEAT_D + d] = __float2bfloat16(wv);
        g_zb[(size_t)j * FEAT_D + d] = __float2bfloat16(zv);
        dw += zv * wv;
        sq += zv * zv;
    }
#pragma unroll
    for (int o = 16; o; o >>= 1) {
        dw += __shfl_xor_sync(0xFFFFFFFFu, dw, o);
        sq += __shfl_xor_sync(0xFFFFFFFFu, sq, o);
    }
    __shared__ float sd[4], ss[4];
    if ((t & 31) == 0) { sd[t >> 5] = dw; ss[t >> 5] = sq; }
    __syncthreads();
    if (t == 0) {
        g_dw[j] = sd[0] + sd[1] + sd[2] + sd[3];
        g_sq[j] = ss[0] + ss[1] + ss[2] + ss[3];
    }
}

// ---------------- K2: dual-Gram HMMA 128x128 tile + fused epilogue ----------------
// 8 warps in a 2(m) x 4(n) grid; warp tile 64(m) x 32(n); per warp: 4 m16-tiles x
// 4 n8-tiles x 2 products, accumulated in registers over K=512.
__global__ __launch_bounds__(256, 1) void k_main() {
    extern __shared__ char smem_raw[];
    uint32_t sbase;
    asm("{ .reg .u64 t; cvta.to.shared.u64 t, %1; cvt.u32.u64 %0, t; }"
        : "=r"(sbase) : "l"(smem_raw));
    const uint32_t abase = (sbase + 1023u) & ~1023u;
    char* ab = smem_raw + (abase - sbase);

    float* s_sqi  = (float*)(ab);
    int*   s_agi  = (int*)(ab + 512);
    float* s_sqj  = (float*)(ab + 1024);
    float* s_dwj  = (float*)(ab + 1536);
    int*   s_agej = (int*)(ab + 2048);
    float* s_red  = (float*)(ab + 2560);

    const int tid  = threadIdx.x;
    const int lane = tid & 31;
    const int wid  = tid >> 5;
    const int wm   = wid >> 2;   // 0..1
    const int wn   = wid & 3;    // 0..3
    const int i0 = blockIdx.y * TI;
    const int j0 = blockIdx.x * TJ;

    if (tid < 128) {
        s_sqj[tid]  = g_sq[j0 + tid];
        s_dwj[tid]  = g_dw[j0 + tid];
        s_agej[tid] = g_ages[j0 + tid];
    } else {
        int r = tid - 128;
        s_sqi[r] = g_sq[i0 + r];
        s_agi[r] = g_ages[i0 + r];
    }

    const uint32_t stg0 = abase + META;

    // ---- stage loader: 3 buffers x 1024 16B-units, 4 units/thread/buffer ----
    auto load_stage = [&](int c) {
        uint32_t st = stg0 + (uint32_t)(c & 1) * STAGE_BYTES;
        int k0 = c * KC;
#pragma unroll
        for (int q = 0; q < 4; ++q) {
            int u   = tid + q * 256;
            int row = u >> 3;
            int un  = u & 7;
            uint32_t d = SW128((uint32_t)(u * 16));
            cp16(st + d,         g_zb + (size_t)(i0 + row) * FEAT_D + k0 + un * 8);
            cp16(st + 16384 + d, g_zb + (size_t)(j0 + row) * FEAT_D + k0 + un * 8);
            cp16(st + 32768 + d, g_wb + (size_t)(j0 + row) * FEAT_D + k0 + un * 8);
        }
        asm volatile("cp.async.commit_group;" ::: "memory");
    };

    load_stage(0);
    load_stage(1);

    float cg[4][4][4] = {};
    float cw[4][4][4] = {};

    const int q8 = lane >> 3;    // 0..3 ldmatrix addr group
    const int lr = lane & 7;

#pragma unroll 1
    for (int c = 0; c < NCHUNK; ++c) {
        if (c == NCHUNK - 1) asm volatile("cp.async.wait_group 0;" ::: "memory");
        else                 asm volatile("cp.async.wait_group 1;" ::: "memory");
        __syncthreads();

        const uint32_t st = stg0 + (uint32_t)(c & 1) * STAGE_BYTES;
        const uint32_t zi = st, zj = st + 16384, wj = st + 32768;

#pragma unroll
        for (int kb = 0; kb < KC; kb += 16) {
            uint32_t a[4][4];
#pragma unroll
            for (int mt = 0; mt < 4; ++mt) {
                int row = wm * 64 + mt * 16 + lr + (q8 & 1) * 8;
                int col = kb + (q8 >> 1) * 8;
                ldsm_x4(a[mt], zi + SW128((uint32_t)(row * 128 + col * 2)));
            }
            uint32_t bz[4][2], bw[4][2];
#pragma unroll
            for (int p = 0; p < 2; ++p) {
                int row = wn * 32 + p * 16 + lr + (q8 >> 1) * 8;
                int col = kb + (q8 & 1) * 8;
                uint32_t off = SW128((uint32_t)(row * 128 + col * 2));
                uint32_t rz[4], rw[4];
                ldsm_x4(rz, zj + off);
                ldsm_x4(rw, wj + off);
                bz[2 * p][0] = rz[0]; bz[2 * p][1] = rz[1];
                bz[2 * p + 1][0] = rz[2]; bz[2 * p + 1][1] = rz[3];
                bw[2 * p][0] = rw[0]; bw[2 * p][1] = rw[1];
                bw[2 * p + 1][0] = rw[2]; bw[2 * p + 1][1] = rw[3];
            }
#pragma unroll
            for (int mt = 0; mt < 4; ++mt)
#pragma unroll
                for (int nt = 0; nt < 4; ++nt) {
                    mma_bf16(cg[mt][nt], a[mt], bz[nt][0], bz[nt][1]);
                    mma_bf16(cw[mt][nt], a[mt], bw[nt][0], bw[nt][1]);
                }
        }

        __syncthreads();
        if (c + 2 < NCHUNK) load_stage(c + 2);
    }

    // ---- epilogue: masked softplus directly on register fragments ----
    const int g  = lane >> 2;
    const int tg = lane & 3;
    float lsum = 0.f;
#pragma unroll
    for (int mt = 0; mt < 4; ++mt) {
        int r0 = wm * 64 + mt * 16 + g;
        float sqi0 = s_sqi[r0],     sqi1 = s_sqi[r0 + 8];
        int   ag0  = s_agi[r0],     ag1  = s_agi[r0 + 8];
#pragma unroll
        for (int nt = 0; nt < 4; ++nt) {
            int cb = wn * 32 + nt * 8 + tg * 2;
#pragma unroll
            for (int h = 0; h < 2; ++h) {
                int cj = cb + h;
                float sqj = s_sqj[cj], dwj = s_dwj[cj];
                int   agj = s_agej[cj];
                if (ag0 < agj) {
                    float G  = cg[mt][nt][h];
                    float Gw = cw[mt][nt][h];
                    float d2 = fmaxf(sqi0 + sqj - 2.f * G, 0.f);
                    float x  = __fdividef((Gw - dwj) * 10.0f, sqrtf(d2) + EPS_F);
                    lsum += fmaxf(x, 0.f) + __logf(1.f + __expf(-fabsf(x)));
                }
                if (ag1 < agj) {
                    float G  = cg[mt][nt][2 + h];
                    float Gw = cw[mt][nt][2 + h];
                    float d2 = fmaxf(sqi1 + sqj - 2.f * G, 0.f);
                    float x  = __fdividef((Gw - dwj) * 10.0f, sqrtf(d2) + EPS_F);
                    lsum += fmaxf(x, 0.f) + __logf(1.f + __expf(-fabsf(x)));
                }
            }
        }
    }

    s_red[tid] = lsum;
    __syncthreads();
#pragma unroll
    for (int s = 128; s > 0; s >>= 1) {
        if (tid < s) s_red[tid] += s_red[tid + s];
        __syncthreads();
    }
    if (tid == 0) atomicAdd(&g_acc, (double)s_red[0]);
}

// ---------------- K3: finalize ----------------
__global__ void k_final(float* __restrict__ out) {
    out[0] = (float)(g_acc / ((double)BATCH_N * (double)(BATCH_N - 1)));
}

extern "C" void kernel_launch(void* const* d_in, const int* in_sizes, int n_in,
                              void* d_out, int out_size) {
    const float* z       = (const float*)d_in[0];
    const void*  ages    = d_in[1];
    const float* proxies = (const float*)d_in[2];
    float* out = (float*)d_out;

    cudaFuncSetAttribute(k_main, cudaFuncAttributeMaxDynamicSharedMemorySize, SMEM_DYN);

    k_init<<<1, 256>>>(ages);
    k_prep<<<BATCH_N, 128>>>(z, proxies);
    dim3 grid(BATCH_N / TJ, BATCH_N / TI);
    k_main<<<grid, 256, SMEM_DYN>>>();
    k_final<<<1, 1>>>(out);
}

// round 4
// speedup vs baseline: 7.7331x; 1.5971x over previous
#include <cuda_runtime.h>
#include <cuda_bf16.h>
#include <math.h>
#include <stdint.h>

#define BATCH_N   4096
#define FEAT_D    512
#define NUM_AGES  100
#define EPS_F     1e-6f

#define TI 128
#define TJ 128
#define NTILE (BATCH_N / 128)              // 32
#define NPAIR (NTILE * (NTILE + 1) / 2)    // 528 upper-triangular tiles
#define KC 64                              // K chunk (bf16 elems) = 128B rows
#define NCHUNK (FEAT_D / KC)               // 8
#define STAGE_BYTES (3 * 128 * 128)        // Zi,Zj,Wj: 3 x 16KB
#define META 4096
#define SMEM_DYN (META + 2 * STAGE_BYTES + 1024)

#define SW128(o) ((o) ^ (((o) >> 3) & 0x70))

// ---------------- device scratch ----------------
__device__ __nv_bfloat16 g_zb[BATCH_N * FEAT_D];   // sorted order
__device__ __nv_bfloat16 g_wb[BATCH_N * FEAT_D];   // sorted order
__device__ float  g_sq[BATCH_N];                   // sorted order
__device__ float  g_dw[BATCH_N];                   // sorted order
__device__ int    g_ages[BATCH_N];                 // sorted (ascending)
__device__ int    g_perm[BATCH_N];                 // sorted pos -> original index
__device__ double g_acc;

// ---------------- PTX helpers (portable at compute_103) ----------------
static __device__ __forceinline__ void ldsm_x4(uint32_t (&r)[4], uint32_t addr) {
    asm volatile("ldmatrix.sync.aligned.m8n8.x4.shared.b16 {%0,%1,%2,%3}, [%4];"
                 : "=r"(r[0]), "=r"(r[1]), "=r"(r[2]), "=r"(r[3]) : "r"(addr));
}
static __device__ __forceinline__ void mma_bf16(float (&c)[4], const uint32_t (&a)[4],
                                                const uint32_t b0, const uint32_t b1) {
    asm volatile(
        "mma.sync.aligned.m16n8k16.row.col.f32.bf16.bf16.f32 "
        "{%0,%1,%2,%3}, {%4,%5,%6,%7}, {%8,%9}, {%0,%1,%2,%3};"
        : "+f"(c[0]), "+f"(c[1]), "+f"(c[2]), "+f"(c[3])
        : "r"(a[0]), "r"(a[1]), "r"(a[2]), "r"(a[3]), "r"(b0), "r"(b1));
}
static __device__ __forceinline__ void cp16(uint32_t dst, const void* src) {
    asm volatile("cp.async.cg.shared.global [%0], [%1], 16;" :: "r"(dst), "l"(src) : "memory");
}

// ---------------- K0: counting sort of samples by age ----------------
// Loss = sum over unordered sample pairs -> permutation invariant, so any order
// within equal ages is exact. Nondeterministic tie order only permutes the
// addition order of identical values (which atomics permute anyway).
__global__ __launch_bounds__(1024) void k_sort(const void* __restrict__ ages_raw) {
    __shared__ int s_is64;
    __shared__ int s_hist[NUM_AGES];
    __shared__ int s_off[NUM_AGES];
    const int t = threadIdx.x;
    if (t == 0) {
        const long long* p = (const long long*)ages_raw;
        int ok = 1;
        for (int q = 0; q < 64; ++q) {
            long long v = p[q];
            if (v < 0 || v >= NUM_AGES) { ok = 0; break; }
        }
        s_is64 = ok;
        g_acc = 0.0;
    }
    if (t < NUM_AGES) s_hist[t] = 0;
    __syncthreads();
    const int is64 = s_is64;

    for (int i = t; i < BATCH_N; i += 1024) {
        int a = is64 ? (int)((const long long*)ages_raw)[i]
                     : ((const int*)ages_raw)[i];
        atomicAdd(&s_hist[a], 1);
    }
    __syncthreads();
    if (t == 0) {
        int run = 0;
        for (int b = 0; b < NUM_AGES; ++b) { s_off[b] = run; run += s_hist[b]; }
    }
    __syncthreads();
    for (int i = t; i < BATCH_N; i += 1024) {
        int a = is64 ? (int)((const long long*)ages_raw)[i]
                     : ((const int*)ages_raw)[i];
        int pos = atomicAdd(&s_off[a], 1);
        g_perm[pos] = i;
        g_ages[pos] = a;
    }
}

// ---------------- K1: w_j (bf16), z (bf16), dw_j, sq_j  (sorted order) ----------------
__global__ __launch_bounds__(128) void k_prep(const float* __restrict__ z,
                                              const float* __restrict__ proxies) {
    const int j    = blockIdx.x;          // sorted position
    const int t    = threadIdx.x;
    const int orig = g_perm[j];
    const int aj = g_ages[j];
    const int an = min(aj + 1, NUM_AGES - 1);
    const int ap = max(aj - 1, 0);
    const float* cc = proxies + (size_t)aj * FEAT_D;
    const float* cn = proxies + (size_t)an * FEAT_D;
    const float* cp = proxies + (size_t)ap * FEAT_D;
    const float* zr = z + (size_t)orig * FEAT_D;

    float df[4], db[4];
    float nf2 = 0.f, nb2 = 0.f;
#pragma unroll
    for (int q = 0; q < 4; ++q) {
        int d = t + q * 128;
        float c0 = cc[d];
        df[q] = cn[d] - c0;
        db[q] = cp[d] - c0;
        nf2 += df[q] * df[q];
        nb2 += db[q] * db[q];
    }
#pragma unroll
    for (int o = 16; o; o >>= 1) {
        nf2 += __shfl_xor_sync(0xFFFFFFFFu, nf2, o);
        nb2 += __shfl_xor_sync(0xFFFFFFFFu, nb2, o);
    }
    __shared__ float sf[4], sb[4];
    if ((t & 31) == 0) { sf[t >> 5] = nf2; sb[t >> 5] = nb2; }
    __syncthreads();
    nf2 = sf[0] + sf[1] + sf[2] + sf[3];
    nb2 = sb[0] + sb[1] + sb[2] + sb[3];
    const float rf = 1.f / (sqrtf(nf2) + EPS_F);
    const float rb = 1.f / (sqrtf(nb2) + EPS_F);

    float dw = 0.f, sq = 0.f;
#pragma unroll
    for (int q = 0; q < 4; ++q) {
        int d = t + q * 128;
        float wv = db[q] * rb - df[q] * rf;
        float zv = zr[d];
        g_wb[(size_t)j * FEAT_D + d] = __float2bfloat16(wv);
        g_zb[(size_t)j * FEAT_D + d] = __float2bfloat16(zv);
        dw += zv * wv;
        sq += zv * zv;
    }
#pragma unroll
    for (int o = 16; o; o >>= 1) {
        dw += __shfl_xor_sync(0xFFFFFFFFu, dw, o);
        sq += __shfl_xor_sync(0xFFFFFFFFu, sq, o);
    }
    __shared__ float sd[4], ss[4];
    if ((t & 31) == 0) { sd[t >> 5] = dw; ss[t >> 5] = sq; }
    __syncthreads();
    if (t == 0) {
        g_dw[j] = sd[0] + sd[1] + sd[2] + sd[3];
        g_sq[j] = ss[0] + ss[1] + ss[2] + ss[3];
    }
}

// ---------------- K2: dual-Gram HMMA, upper-triangular tiles only ----------------
__global__ __launch_bounds__(256, 1) void k_main() {
    extern __shared__ char smem_raw[];
    uint32_t sbase;
    asm("{ .reg .u64 t; cvta.to.shared.u64 t, %1; cvt.u32.u64 %0, t; }"
        : "=r"(sbase) : "l"(smem_raw));
    const uint32_t abase = (sbase + 1023u) & ~1023u;
    char* ab = smem_raw + (abase - sbase);

    float* s_sqi  = (float*)(ab);
    int*   s_agi  = (int*)(ab + 512);
    float* s_sqj  = (float*)(ab + 1024);
    float* s_dwj  = (float*)(ab + 1536);
    int*   s_agej = (int*)(ab + 2048);
    float* s_red  = (float*)(ab + 2560);

    // map linear block -> (I, J) with I <= J (upper triangle incl. diagonal)
    int b = blockIdx.x;
    int I = 0;
    while (b >= NTILE - I) { b -= NTILE - I; ++I; }
    const int J = I + b;
    const int i0 = I * TI;
    const int j0 = J * TJ;

    const int tid  = threadIdx.x;
    const int lane = tid & 31;
    const int wid  = tid >> 5;
    const int wm   = wid >> 2;   // 0..1
    const int wn   = wid & 3;    // 0..3

    if (tid < 128) {
        s_sqj[tid]  = g_sq[j0 + tid];
        s_dwj[tid]  = g_dw[j0 + tid];
        s_agej[tid] = g_ages[j0 + tid];
    } else {
        int r = tid - 128;
        s_sqi[r] = g_sq[i0 + r];
        s_agi[r] = g_ages[i0 + r];
    }

    const uint32_t stg0 = abase + META;

    auto load_stage = [&](int c) {
        uint32_t st = stg0 + (uint32_t)(c & 1) * STAGE_BYTES;
        int k0 = c * KC;
#pragma unroll
        for (int q = 0; q < 4; ++q) {
            int u   = tid + q * 256;
            int row = u >> 3;
            int un  = u & 7;
            uint32_t d = SW128((uint32_t)(u * 16));
            cp16(st + d,         g_zb + (size_t)(i0 + row) * FEAT_D + k0 + un * 8);
            cp16(st + 16384 + d, g_zb + (size_t)(j0 + row) * FEAT_D + k0 + un * 8);
            cp16(st + 32768 + d, g_wb + (size_t)(j0 + row) * FEAT_D + k0 + un * 8);
        }
        asm volatile("cp.async.commit_group;" ::: "memory");
    };

    load_stage(0);
    load_stage(1);

    float cg[4][4][4] = {};
    float cw[4][4][4] = {};

    const int q8 = lane >> 3;
    const int lr = lane & 7;

#pragma unroll 1
    for (int c = 0; c < NCHUNK; ++c) {
        if (c == NCHUNK - 1) asm volatile("cp.async.wait_group 0;" ::: "memory");
        else                 asm volatile("cp.async.wait_group 1;" ::: "memory");
        __syncthreads();

        const uint32_t st = stg0 + (uint32_t)(c & 1) * STAGE_BYTES;
        const uint32_t zi = st, zj = st + 16384, wj = st + 32768;

#pragma unroll
        for (int kb = 0; kb < KC; kb += 16) {
            uint32_t a[4][4];
#pragma unroll
            for (int mt = 0; mt < 4; ++mt) {
                int row = wm * 64 + mt * 16 + lr + (q8 & 1) * 8;
                int col = kb + (q8 >> 1) * 8;
                ldsm_x4(a[mt], zi + SW128((uint32_t)(row * 128 + col * 2)));
            }
            uint32_t bz[4][2], bw[4][2];
#pragma unroll
            for (int p = 0; p < 2; ++p) {
                int row = wn * 32 + p * 16 + lr + (q8 >> 1) * 8;
                int col = kb + (q8 & 1) * 8;
                uint32_t off = SW128((uint32_t)(row * 128 + col * 2));
                uint32_t rz[4], rw[4];
                ldsm_x4(rz, zj + off);
                ldsm_x4(rw, wj + off);
                bz[2 * p][0] = rz[0]; bz[2 * p][1] = rz[1];
                bz[2 * p + 1][0] = rz[2]; bz[2 * p + 1][1] = rz[3];
                bw[2 * p][0] = rw[0]; bw[2 * p][1] = rw[1];
                bw[2 * p + 1][0] = rw[2]; bw[2 * p + 1][1] = rw[3];
            }
#pragma unroll
            for (int mt = 0; mt < 4; ++mt)
#pragma unroll
                for (int nt = 0; nt < 4; ++nt) {
                    mma_bf16(cg[mt][nt], a[mt], bz[nt][0], bz[nt][1]);
                    mma_bf16(cw[mt][nt], a[mt], bw[nt][0], bw[nt][1]);
                }
        }

        __syncthreads();
        if (c + 2 < NCHUNK) load_stage(c + 2);
    }

    // ---- epilogue: masked softplus on register fragments ----
    const int g  = lane >> 2;
    const int tg = lane & 3;
    float lsum = 0.f;
#pragma unroll
    for (int mt = 0; mt < 4; ++mt) {
        int r0 = wm * 64 + mt * 16 + g;
        float sqi0 = s_sqi[r0],     sqi1 = s_sqi[r0 + 8];
        int   ag0  = s_agi[r0],     ag1  = s_agi[r0 + 8];
#pragma unroll
        for (int nt = 0; nt < 4; ++nt) {
            int cb = wn * 32 + nt * 8 + tg * 2;
#pragma unroll
            for (int h = 0; h < 2; ++h) {
                int cj = cb + h;
                float sqj = s_sqj[cj], dwj = s_dwj[cj];
                int   agj = s_agej[cj];
                if (ag0 < agj) {
                    float G  = cg[mt][nt][h];
                    float Gw = cw[mt][nt][h];
                    float d2 = fmaxf(sqi0 + sqj - 2.f * G, 0.f);
                    float x  = __fdividef((Gw - dwj) * 10.0f, sqrtf(d2) + EPS_F);
                    lsum += fmaxf(x, 0.f) + __logf(1.f + __expf(-fabsf(x)));
                }
                if (ag1 < agj) {
                    float G  = cg[mt][nt][2 + h];
                    float Gw = cw[mt][nt][2 + h];
                    float d2 = fmaxf(sqi1 + sqj - 2.f * G, 0.f);
                    float x  = __fdividef((Gw - dwj) * 10.0f, sqrtf(d2) + EPS_F);
                    lsum += fmaxf(x, 0.f) + __logf(1.f + __expf(-fabsf(x)));
                }
            }
        }
    }

    s_red[tid] = lsum;
    __syncthreads();
#pragma unroll
    for (int s = 128; s > 0; s >>= 1) {
        if (tid < s) s_red[tid] += s_red[tid + s];
        __syncthreads();
    }
    if (tid == 0) atomicAdd(&g_acc, (double)s_red[0]);
}

// ---------------- K3: finalize ----------------
__global__ void k_final(float* __restrict__ out) {
    out[0] = (float)(g_acc / ((double)BATCH_N * (double)(BATCH_N - 1)));
}

extern "C" void kernel_launch(void* const* d_in, const int* in_sizes, int n_in,
                              void* d_out, int out_size) {
    const float* z       = (const float*)d_in[0];
    const void*  ages    = d_in[1];
    const float* proxies = (const float*)d_in[2];
    float* out = (float*)d_out;

    cudaFuncSetAttribute(k_main, cudaFuncAttributeMaxDynamicSharedMemorySize, SMEM_DYN);

    k_sort<<<1, 1024>>>(ages);
    k_prep<<<BATCH_N, 128>>>(z, proxies);
    k_main<<<NPAIR, 256, SMEM_DYN>>>();
    k_final<<<1, 1>>>(out);
}

// round 5
// speedup vs baseline: 8.2446x; 1.0661x over previous
#include <cuda_runtime.h>
#include <cuda_bf16.h>
#include <math.h>
#include <stdint.h>

#define BATCH_N   4096
#define FEAT_D    512
#define NUM_AGES  100
#define EPS_F     1e-6f

#define TI 64
#define TJ 128
#define NJT (BATCH_N / TJ)                 // 32
#define NPAIR (NJT * NJT + NJT)            // 1056 tiles: J=0..31, I=0..2J+1
#define KC 64                              // K chunk (bf16) = 128B rows
#define NCHUNK (FEAT_D / KC)               // 8
#define STAGE_BYTES 40960                  // Zi 8KB + Zj 16KB + Wj 16KB
#define META 4096
#define SMEM_DYN (META + 2 * STAGE_BYTES + 1024)

#define SW128(o) ((o) ^ (((o) >> 3) & 0x70))

// ---------------- device scratch ----------------
__device__ __nv_bfloat16 g_zb[BATCH_N * FEAT_D];   // age-sorted
__device__ __nv_bfloat16 g_wb[BATCH_N * FEAT_D];   // age-sorted
__device__ float  g_sq[BATCH_N];
__device__ float  g_dw[BATCH_N];
__device__ int    g_ages[BATCH_N];                 // ascending
__device__ int    g_perm[BATCH_N];
__device__ double g_acc;

// ---------------- PTX helpers ----------------
static __device__ __forceinline__ void ldsm_x4(uint32_t (&r)[4], uint32_t addr) {
    asm volatile("ldmatrix.sync.aligned.m8n8.x4.shared.b16 {%0,%1,%2,%3}, [%4];"
                 : "=r"(r[0]), "=r"(r[1]), "=r"(r[2]), "=r"(r[3]) : "r"(addr));
}
static __device__ __forceinline__ void mma_bf16(float (&c)[4], const uint32_t (&a)[4],
                                                const uint32_t b0, const uint32_t b1) {
    asm volatile(
        "mma.sync.aligned.m16n8k16.row.col.f32.bf16.bf16.f32 "
        "{%0,%1,%2,%3}, {%4,%5,%6,%7}, {%8,%9}, {%0,%1,%2,%3};"
        : "+f"(c[0]), "+f"(c[1]), "+f"(c[2]), "+f"(c[3])
        : "r"(a[0]), "r"(a[1]), "r"(a[2]), "r"(a[3]), "r"(b0), "r"(b1));
}
static __device__ __forceinline__ void cp16(uint32_t dst, const void* src) {
    asm volatile("cp.async.cg.shared.global [%0], [%1], 16;" :: "r"(dst), "l"(src) : "memory");
}

// ---------------- K0: counting sort by age (permutation-invariant loss) ----------------
__global__ __launch_bounds__(1024) void k_sort(const void* __restrict__ ages_raw) {
    __shared__ int s_is64;
    __shared__ int s_hist[NUM_AGES];
    __shared__ int s_off[NUM_AGES];
    const int t = threadIdx.x;
    if (t == 0) {
        const long long* p = (const long long*)ages_raw;
        int ok = 1;
        for (int q = 0; q < 64; ++q) {
            long long v = p[q];
            if (v < 0 || v >= NUM_AGES) { ok = 0; break; }
        }
        s_is64 = ok;
        g_acc = 0.0;
    }
    if (t < NUM_AGES) s_hist[t] = 0;
    __syncthreads();
    const int is64 = s_is64;

    for (int i = t; i < BATCH_N; i += 1024) {
        int a = is64 ? (int)((const long long*)ages_raw)[i]
                     : ((const int*)ages_raw)[i];
        atomicAdd(&s_hist[a], 1);
    }
    __syncthreads();
    if (t == 0) {
        int run = 0;
        for (int b = 0; b < NUM_AGES; ++b) { s_off[b] = run; run += s_hist[b]; }
    }
    __syncthreads();
    for (int i = t; i < BATCH_N; i += 1024) {
        int a = is64 ? (int)((const long long*)ages_raw)[i]
                     : ((const int*)ages_raw)[i];
        int pos = atomicAdd(&s_off[a], 1);
        g_perm[pos] = i;
        g_ages[pos] = a;
    }
}

// ---------------- K1: w_j (bf16), z (bf16), dw_j, sq_j (sorted order) ----------------
__global__ __launch_bounds__(128) void k_prep(const float* __restrict__ z,
                                              const float* __restrict__ proxies) {
    const int j    = blockIdx.x;
    const int t    = threadIdx.x;
    const int orig = g_perm[j];
    const int aj = g_ages[j];
    const int an = min(aj + 1, NUM_AGES - 1);
    const int ap = max(aj - 1, 0);
    const float* cc = proxies + (size_t)aj * FEAT_D;
    const float* cn = proxies + (size_t)an * FEAT_D;
    const float* cp = proxies + (size_t)ap * FEAT_D;
    const float* zr = z + (size_t)orig * FEAT_D;

    float df[4], db[4];
    float nf2 = 0.f, nb2 = 0.f;
#pragma unroll
    for (int q = 0; q < 4; ++q) {
        int d = t + q * 128;
        float c0 = cc[d];
        df[q] = cn[d] - c0;
        db[q] = cp[d] - c0;
        nf2 += df[q] * df[q];
        nb2 += db[q] * db[q];
    }
#pragma unroll
    for (int o = 16; o; o >>= 1) {
        nf2 += __shfl_xor_sync(0xFFFFFFFFu, nf2, o);
        nb2 += __shfl_xor_sync(0xFFFFFFFFu, nb2, o);
    }
    __shared__ float sf[4], sb[4];
    if ((t & 31) == 0) { sf[t >> 5] = nf2; sb[t >> 5] = nb2; }
    __syncthreads();
    nf2 = sf[0] + sf[1] + sf[2] + sf[3];
    nb2 = sb[0] + sb[1] + sb[2] + sb[3];
    const float rf = 1.f / (sqrtf(nf2) + EPS_F);
    const float rb = 1.f / (sqrtf(nb2) + EPS_F);

    float dw = 0.f, sq = 0.f;
#pragma unroll
    for (int q = 0; q < 4; ++q) {
        int d = t + q * 128;
        float wv = db[q] * rb - df[q] * rf;
        float zv = zr[d];
        g_wb[(size_t)j * FEAT_D + d] = __float2bfloat16(wv);
        g_zb[(size_t)j * FEAT_D + d] = __float2bfloat16(zv);
        dw += zv * wv;
        sq += zv * zv;
    }
#pragma unroll
    for (int o = 16; o; o >>= 1) {
        dw += __shfl_xor_sync(0xFFFFFFFFu, dw, o);
        sq += __shfl_xor_sync(0xFFFFFFFFu, sq, o);
    }
    __shared__ float sd[4], ss[4];
    if ((t & 31) == 0) { sd[t >> 5] = dw; ss[t >> 5] = sq; }
    __syncthreads();
    if (t == 0) {
        g_dw[j] = sd[0] + sd[1] + sd[2] + sd[3];
        g_sq[j] = ss[0] + ss[1] + ss[2] + ss[3];
    }
}

// ---------------- K2: dual-Gram HMMA, 64x128 tiles, 2 CTAs/SM ----------------
// 4 warps (wn = wid), warp tile 64(m) x 32(n); per warp 4 m-tiles x 4 n-tiles x 2.
__global__ __launch_bounds__(128, 2) void k_main() {
    extern __shared__ char smem_raw[];
    uint32_t sbase;
    asm("{ .reg .u64 t; cvta.to.shared.u64 t, %1; cvt.u32.u64 %0, t; }"
        : "=r"(sbase) : "l"(smem_raw));
    const uint32_t abase = (sbase + 1023u) & ~1023u;
    char* ab = smem_raw + (abase - sbase);

    float* s_sqi  = (float*)(ab);            // 64
    int*   s_agi  = (int*)(ab + 256);        // 64
    float* s_sqj  = (float*)(ab + 512);      // 128
    float* s_dwj  = (float*)(ab + 1024);     // 128
    int*   s_agej = (int*)(ab + 1536);       // 128
    float* s_red  = (float*)(ab + 2048);     // 128

    // linear block -> (I, J):  J has tiles I = 0..2J+1 ; cum(J) = J^2 + J
    int b = blockIdx.x;
    int J = (int)((sqrtf(4.0f * (float)b + 1.0f) - 1.0f) * 0.5f);
    while ((J + 1) * (J + 1) + (J + 1) <= b) ++J;
    while (J * J + J > b) --J;
    const int I  = b - (J * J + J);
    const int i0 = I * TI;
    const int j0 = J * TJ;

    const int tid  = threadIdx.x;
    const int lane = tid & 31;
    const int wn   = tid >> 5;   // 0..3

    if (tid < 64) {
        s_sqi[tid] = g_sq[i0 + tid];
        s_agi[tid] = g_ages[i0 + tid];
    }
    {
        s_sqj[tid]  = g_sq[j0 + tid];
        s_dwj[tid]  = g_dw[j0 + tid];
        s_agej[tid] = g_ages[j0 + tid];
    }

    const uint32_t stg0 = abase + META;

    auto load_stage = [&](int c) {
        uint32_t st = stg0 + (uint32_t)(c & 1) * STAGE_BYTES;
        int k0 = c * KC;
#pragma unroll
        for (int q = 0; q < 4; ++q) {      // Zi: 512 units
            int u = tid + q * 128;
            int row = u >> 3, un = u & 7;
            cp16(st + SW128((uint32_t)(u * 16)),
                 g_zb + (size_t)(i0 + row) * FEAT_D + k0 + un * 8);
        }
#pragma unroll
        for (int q = 0; q < 8; ++q) {      // Zj + Wj: 1024 units each
            int u = tid + q * 128;
            int row = u >> 3, un = u & 7;
            uint32_t d = SW128((uint32_t)(u * 16));
            cp16(st + 8192  + d, g_zb + (size_t)(j0 + row) * FEAT_D + k0 + un * 8);
            cp16(st + 24576 + d, g_wb + (size_t)(j0 + row) * FEAT_D + k0 + un * 8);
        }
        asm volatile("cp.async.commit_group;" ::: "memory");
    };

    load_stage(0);
    load_stage(1);

    float cg[4][4][4] = {};
    float cw[4][4][4] = {};

    const int q8 = lane >> 3;
    const int lr = lane & 7;

#pragma unroll 1
    for (int c = 0; c < NCHUNK; ++c) {
        if (c == NCHUNK - 1) asm volatile("cp.async.wait_group 0;" ::: "memory");
        else                 asm volatile("cp.async.wait_group 1;" ::: "memory");
        __syncthreads();

        const uint32_t st = stg0 + (uint32_t)(c & 1) * STAGE_BYTES;
        const uint32_t zi = st, zj = st + 8192, wj = st + 24576;

#pragma unroll
        for (int kb = 0; kb < KC; kb += 16) {
            uint32_t a[4][4];
#pragma unroll
            for (int mt = 0; mt < 4; ++mt) {
                int row = mt * 16 + lr + (q8 & 1) * 8;
                int col = kb + (q8 >> 1) * 8;
                ldsm_x4(a[mt], zi + SW128((uint32_t)(row * 128 + col * 2)));
            }
            uint32_t bz[4][2], bw[4][2];
#pragma unroll
            for (int p = 0; p < 2; ++p) {
                int row = wn * 32 + p * 16 + lr + (q8 >> 1) * 8;
                int col = kb + (q8 & 1) * 8;
                uint32_t off = SW128((uint32_t)(row * 128 + col * 2));
                uint32_t rz[4], rw[4];
                ldsm_x4(rz, zj + off);
                ldsm_x4(rw, wj + off);
                bz[2 * p][0] = rz[0]; bz[2 * p][1] = rz[1];
                bz[2 * p + 1][0] = rz[2]; bz[2 * p + 1][1] = rz[3];
                bw[2 * p][0] = rw[0]; bw[2 * p][1] = rw[1];
                bw[2 * p + 1][0] = rw[2]; bw[2 * p + 1][1] = rw[3];
            }
#pragma unroll
            for (int mt = 0; mt < 4; ++mt)
#pragma unroll
                for (int nt = 0; nt < 4; ++nt) {
                    mma_bf16(cg[mt][nt], a[mt], bz[nt][0], bz[nt][1]);
                    mma_bf16(cw[mt][nt], a[mt], bw[nt][0], bw[nt][1]);
                }
        }

        __syncthreads();
        if (c + 2 < NCHUNK) load_stage(c + 2);
    }

    // ---- epilogue: masked softplus on register fragments ----
    const int g  = lane >> 2;
    const int tg = lane & 3;
    float lsum = 0.f;
#pragma unroll
    for (int mt = 0; mt < 4; ++mt) {
        int r0 = mt * 16 + g;
        float sqi0 = s_sqi[r0],     sqi1 = s_sqi[r0 + 8];
        int   ag0  = s_agi[r0],     ag1  = s_agi[r0 + 8];
#pragma unroll
        for (int nt = 0; nt < 4; ++nt) {
            int cb = wn * 32 + nt * 8 + tg * 2;
#pragma unroll
            for (int h = 0; h < 2; ++h) {
                int cj = cb + h;
                float sqj = s_sqj[cj], dwj = s_dwj[cj];
                int   agj = s_agej[cj];
                if (ag0 < agj) {
                    float G  = cg[mt][nt][h];
                    float Gw = cw[mt][nt][h];
                    float d2 = fmaxf(sqi0 + sqj - 2.f * G, 0.f);
                    float x  = __fdividef((Gw - dwj) * 10.0f, sqrtf(d2) + EPS_F);
                    lsum += fmaxf(x, 0.f) + __logf(1.f + __expf(-fabsf(x)));
                }
                if (ag1 < agj) {
                    float G  = cg[mt][nt][2 + h];
                    float Gw = cw[mt][nt][2 + h];
                    float d2 = fmaxf(sqi1 + sqj - 2.f * G, 0.f);
                    float x  = __fdividef((Gw - dwj) * 10.0f, sqrtf(d2) + EPS_F);
                    lsum += fmaxf(x, 0.f) + __logf(1.f + __expf(-fabsf(x)));
                }
            }
        }
    }

    s_red[tid] = lsum;
    __syncthreads();
#pragma unroll
    for (int s = 64; s > 0; s >>= 1) {
        if (tid < s) s_red[tid] += s_red[tid + s];
        __syncthreads();
    }
    if (tid == 0) atomicAdd(&g_acc, (double)s_red[0]);
}

// ---------------- K3: finalize ----------------
__global__ void k_final(float* __restrict__ out) {
    out[0] = (float)(g_acc / ((double)BATCH_N * (double)(BATCH_N - 1)));
}

extern "C" void kernel_launch(void* const* d_in, const int* in_sizes, int n_in,
                              void* d_out, int out_size) {
    const float* z       = (const float*)d_in[0];
    const void*  ages    = d_in[1];
    const float* proxies = (const float*)d_in[2];
    float* out = (float*)d_out;

    cudaFuncSetAttribute(k_main, cudaFuncAttributeMaxDynamicSharedMemorySize, SMEM_DYN);

    k_sort<<<1, 1024>>>(ages);
    k_prep<<<BATCH_N, 128>>>(z, proxies);
    k_main<<<NPAIR, 128, SMEM_DYN>>>();
    k_final<<<1, 1>>>(out);
}